// round 5
// baseline (speedup 1.0000x reference)
#include <cuda_runtime.h>

#define CH 64
#define MAXN 65536
#define MAXE 1100000

// Scratch (no allocs allowed).
__device__ int   g_deg[MAXN];
__device__ int   g_off[MAXN];
__device__ int   g_cursor[MAXN];
__device__ int   g_csr[MAXE];
__device__ int   g_total;
__device__ float g_colsum[CH];
__device__ float g_sumsq[CH];
__device__ int   g_idx64;

#define FFMA2(acc, a, b) \
    asm("fma.rn.f32x2 %0, %1, %2, %0;" : "+l"(acc) : "l"(a), "l"(b))
#define PACK2(out, lo, hi) \
    asm("mov.b64 %0, {%1, %2};" : "=l"(out) : "f"(lo), "f"(hi))
#define UNPACK2(lo, hi, in) \
    asm("mov.b64 {%0, %1}, %2;" : "=f"(lo), "=f"(hi) : "l"(in))

// ---------------------------------------------------------------------------
// K1: zero counters + reduction buffers, detect index dtype.
// ---------------------------------------------------------------------------
__global__ void k_init(const int* __restrict__ ei32, int N, int E) {
    for (int i = blockIdx.x * blockDim.x + threadIdx.x; i < N;
         i += gridDim.x * blockDim.x)
        g_deg[i] = 0;
    if (blockIdx.x == 0) {
        if (threadIdx.x < CH) {
            g_colsum[threadIdx.x] = 0.f;
            g_sumsq[threadIdx.x]  = 0.f;
        }
        if (threadIdx.x == 0) {
            g_total = 0;
            // int64 edge_index => high 32-bit word of every entry is 0.
            int allz = 1;
            int cnt = (E < 64) ? E : 64;
            for (int t = 0; t < cnt; t++) allz &= (ei32[2 * t + 1] == 0);
            g_idx64 = allz;
        }
    }
}

// ---------------------------------------------------------------------------
// K2: degree histogram, 4 edges/thread for MLP=4 on the load->atomic chains.
// ---------------------------------------------------------------------------
__global__ void k_hist(const void* __restrict__ ei, int E) {
    const int idx64 = g_idx64;
    const long long* e64 = (const long long*)ei;
    const int*       e32 = (const int*)ei;
    int i0 = (blockIdx.x * blockDim.x + threadIdx.x) * 4;
    int dst[4];
    #pragma unroll
    for (int k = 0; k < 4; k++) {
        int i = i0 + k;
        dst[k] = (i < E) ? (idx64 ? (int)e64[E + i] : e32[E + i]) : -1;
    }
    #pragma unroll
    for (int k = 0; k < 4; k++)
        if (dst[k] >= 0) atomicAdd(&g_deg[dst[k]], 1);
}

// ---------------------------------------------------------------------------
// K3: single-kernel offsets: block-local smem scan + atomic block base.
// ---------------------------------------------------------------------------
__global__ void k_off(int N) {
    __shared__ int s[1024];
    __shared__ int sbase;
    int tid = threadIdx.x;
    int i = blockIdx.x * 1024 + tid;
    int v = (i < N) ? g_deg[i] : 0;
    s[tid] = v;
    __syncthreads();
    for (int o = 1; o < 1024; o <<= 1) {
        int t = (tid >= o) ? s[tid - o] : 0;
        __syncthreads();
        s[tid] += t;
        __syncthreads();
    }
    if (tid == 1023) sbase = atomicAdd(&g_total, s[1023]);
    __syncthreads();
    if (i < N) {
        int o = sbase + s[tid] - v;
        g_off[i] = o;
        g_cursor[i] = o;
    }
}

// ---------------------------------------------------------------------------
// K4: CSR fill, 4 edges/thread (4 independent load->atomic->store chains).
// ---------------------------------------------------------------------------
__global__ void k_fill(const void* __restrict__ ei, int E) {
    const int idx64 = g_idx64;
    const long long* e64 = (const long long*)ei;
    const int*       e32 = (const int*)ei;
    int i0 = (blockIdx.x * blockDim.x + threadIdx.x) * 4;
    int src[4], dst[4];
    #pragma unroll
    for (int k = 0; k < 4; k++) {
        int i = i0 + k;
        if (i < E) {
            if (idx64) { src[k] = (int)e64[i]; dst[k] = (int)e64[E + i]; }
            else       { src[k] = e32[i];      dst[k] = e32[E + i]; }
        } else dst[k] = -1;
    }
    int p[4];
    #pragma unroll
    for (int k = 0; k < 4; k++)
        if (dst[k] >= 0) p[k] = atomicAdd(&g_cursor[dst[k]], 1);
    #pragma unroll
    for (int k = 0; k < 4; k++)
        if (dst[k] >= 0) g_csr[p[k]] = src[k];
}

// ---------------------------------------------------------------------------
// Packed-pair 64x64 GEMM (f32x2): FFMA-pipe instrs halved; packs on ALU pipe.
// ---------------------------------------------------------------------------
__device__ __forceinline__ void gemm64_packed(
    const float4* __restrict__ wa, const float4* __restrict__ wb,
    const float* __restrict__ hrow0, const float* __restrict__ hrow1,
    const float* __restrict__ hrow2, const float* __restrict__ hrow3,
    float* a0, float* a1) {
    unsigned long long pa[2][2] = {{0ull, 0ull}, {0ull, 0ull}};
    const float4* h[4] = {
        reinterpret_cast<const float4*>(hrow0),
        reinterpret_cast<const float4*>(hrow1),
        reinterpret_cast<const float4*>(hrow2),
        reinterpret_cast<const float4*>(hrow3)};
    #pragma unroll
    for (int kk = 0; kk < 16; kk++) {
        float4 va = wa[kk];
        float4 vb = wb[kk];
        unsigned long long wax, way, waz, waw, wbx, wby, wbz, wbw;
        PACK2(wax, va.x, va.x); PACK2(way, va.y, va.y);
        PACK2(waz, va.z, va.z); PACK2(waw, va.w, va.w);
        PACK2(wbx, vb.x, vb.x); PACK2(wby, vb.y, vb.y);
        PACK2(wbz, vb.z, vb.z); PACK2(wbw, vb.w, vb.w);
        #pragma unroll
        for (int p = 0; p < 2; p++) {
            float4 h0 = h[2 * p][kk];
            float4 h1 = h[2 * p + 1][kk];
            unsigned long long hx, hy, hz, hw;
            PACK2(hx, h0.x, h1.x); PACK2(hy, h0.y, h1.y);
            PACK2(hz, h0.z, h1.z); PACK2(hw, h0.w, h1.w);
            FFMA2(pa[p][0], hx, wax); FFMA2(pa[p][0], hy, way);
            FFMA2(pa[p][0], hz, waz); FFMA2(pa[p][0], hw, waw);
            FFMA2(pa[p][1], hx, wbx); FFMA2(pa[p][1], hy, wby);
            FFMA2(pa[p][1], hz, wbz); FFMA2(pa[p][1], hw, wbw);
        }
    }
    #pragma unroll
    for (int p = 0; p < 2; p++) {
        UNPACK2(a0[2 * p], a0[2 * p + 1], pa[p][0]);
        UNPACK2(a1[2 * p], a1[2 * p + 1], pa[p][1]);
    }
}

// ---------------------------------------------------------------------------
// K5: fused gather + MLP + GraphNorm partial sums. Warp handles 4 rows.
// launch_bounds(256,3): 3 CTAs/SM to hide the L2 gather latency.
// ---------------------------------------------------------------------------
__global__ void __launch_bounds__(256, 3)
k_mlp(const float* __restrict__ x,
      const float* __restrict__ W0, const float* __restrict__ ln0w,
      const float* __restrict__ ln0b, const float* __restrict__ W1,
      const float* __restrict__ ln1w, const float* __restrict__ ln1b,
      float* __restrict__ out, int N) {
    __shared__ __align__(16) float sW0[CH][68];
    __shared__ __align__(16) float sW1[CH][68];
    __shared__ __align__(16) float hbuf[8][4][CH];
    __shared__ float bsum[CH];
    __shared__ float bss[CH];

    const int tid  = threadIdx.x;
    const int lane = tid & 31;
    const int warp = tid >> 5;

    for (int i = tid; i < CH * CH; i += blockDim.x) {
        sW0[i >> 6][i & 63] = W0[i];
        sW1[i >> 6][i & 63] = W1[i];
    }
    if (tid < CH) { bsum[tid] = 0.f; bss[tid] = 0.f; }
    #pragma unroll
    for (int r = 0; r < 4; r++) {
        hbuf[warp][r][lane] = 0.f;
        hbuf[warp][r][lane + 32] = 0.f;
    }

    const float w0a = ln0w[lane], w0b = ln0w[lane + 32];
    const float b0a = ln0b[lane], b0b = ln0b[lane + 32];
    const float w1a = ln1w[lane], w1b = ln1w[lane + 32];
    const float b1a = ln1b[lane], b1b = ln1b[lane + 32];
    __syncthreads();

    const float4* wa0 = reinterpret_cast<const float4*>(&sW0[lane][0]);
    const float4* wb0 = reinterpret_cast<const float4*>(&sW0[lane + 32][0]);
    const float4* wa1 = reinterpret_cast<const float4*>(&sW1[lane][0]);
    const float4* wb1 = reinterpret_cast<const float4*>(&sW1[lane + 32][0]);
    const float2* x2  = reinterpret_cast<const float2*>(x);

    float cs0 = 0.f, cs1 = 0.f, ss0 = 0.f, ss1 = 0.f;

    const int gwarp  = blockIdx.x * 8 + warp;
    const int nwarps = gridDim.x * 8;

    for (int base = gwarp * 4; base < N; base += nwarps * 4) {
        // ---- gather: h = x[row] + sum of neighbor rows.
        //      unroll x2 with two independent accumulators (MLP + FADD ILP).
        #pragma unroll
        for (int r = 0; r < 4; r++) {
            int row = base + r;
            if (row < N) {
                int off = g_off[row];
                int deg = g_deg[row];
                float2 acc0 = x2[row * 32 + lane];
                float2 acc1 = make_float2(0.f, 0.f);
                int j = 0;
                for (; j + 2 <= deg; j += 2) {
                    int s0 = g_csr[off + j];
                    int s1 = g_csr[off + j + 1];
                    float2 v0 = x2[s0 * 32 + lane];
                    float2 v1 = x2[s1 * 32 + lane];
                    acc0.x += v0.x; acc0.y += v0.y;
                    acc1.x += v1.x; acc1.y += v1.y;
                }
                if (j < deg) {
                    int s0 = g_csr[off + j];
                    float2 v0 = x2[s0 * 32 + lane];
                    acc0.x += v0.x; acc0.y += v0.y;
                }
                acc0.x += acc1.x; acc0.y += acc1.y;
                reinterpret_cast<float2*>(&hbuf[warp][r][0])[lane] = acc0;
            }
        }
        __syncwarp();

        // ---- layer 0 GEMM ----
        float a0[4], a1[4];
        gemm64_packed(wa0, wb0, &hbuf[warp][0][0], &hbuf[warp][1][0],
                      &hbuf[warp][2][0], &hbuf[warp][3][0], a0, a1);
        __syncwarp();

        // ---- LayerNorm 0 + ReLU, restage ----
        #pragma unroll
        for (int r = 0; r < 4; r++) {
            float s = a0[r] + a1[r];
            #pragma unroll
            for (int o = 16; o; o >>= 1) s += __shfl_xor_sync(0xffffffffu, s, o);
            float mu = s * (1.f / 64.f);
            float d0 = a0[r] - mu, d1 = a1[r] - mu;
            float q = d0 * d0 + d1 * d1;
            #pragma unroll
            for (int o = 16; o; o >>= 1) q += __shfl_xor_sync(0xffffffffu, q, o);
            float inv = rsqrtf(q * (1.f / 64.f) + 1e-5f);
            hbuf[warp][r][lane]      = fmaxf(fmaf(d0 * inv, w0a, b0a), 0.f);
            hbuf[warp][r][lane + 32] = fmaxf(fmaf(d1 * inv, w0b, b0b), 0.f);
        }
        __syncwarp();

        // ---- layer 1 GEMM ----
        gemm64_packed(wa1, wb1, &hbuf[warp][0][0], &hbuf[warp][1][0],
                      &hbuf[warp][2][0], &hbuf[warp][3][0], a0, a1);

        // ---- LayerNorm 1 + ReLU + store + GraphNorm partials ----
        #pragma unroll
        for (int r = 0; r < 4; r++) {
            int row = base + r;
            float s = a0[r] + a1[r];
            #pragma unroll
            for (int o = 16; o; o >>= 1) s += __shfl_xor_sync(0xffffffffu, s, o);
            float mu = s * (1.f / 64.f);
            float d0 = a0[r] - mu, d1 = a1[r] - mu;
            float q = d0 * d0 + d1 * d1;
            #pragma unroll
            for (int o = 16; o; o >>= 1) q += __shfl_xor_sync(0xffffffffu, q, o);
            float inv = rsqrtf(q * (1.f / 64.f) + 1e-5f);
            float v0 = fmaxf(fmaf(d0 * inv, w1a, b1a), 0.f);
            float v1 = fmaxf(fmaf(d1 * inv, w1b, b1b), 0.f);
            if (row < N) {
                float* orow = out + (size_t)row * CH;
                orow[lane]      = v0;
                orow[lane + 32] = v1;
                cs0 += v0; cs1 += v1;
                ss0 = fmaf(v0, v0, ss0);
                ss1 = fmaf(v1, v1, ss1);
            }
        }
        __syncwarp();
    }

    // column sum / sumsq partials: register -> shared -> 128 global atomics.
    atomicAdd(&bsum[lane], cs0);
    atomicAdd(&bsum[lane + 32], cs1);
    atomicAdd(&bss[lane], ss0);
    atomicAdd(&bss[lane + 32], ss1);
    __syncthreads();
    if (tid < CH) {
        atomicAdd(&g_colsum[tid], bsum[tid]);
        atomicAdd(&g_sumsq[tid],  bss[tid]);
    }
}

// ---------------------------------------------------------------------------
// K6: final GraphNorm, in-place, float4. var = E[h^2] - 2*am*mu + am^2.
// ---------------------------------------------------------------------------
__global__ void k_final(const float* __restrict__ gnw, const float* __restrict__ gnb,
                        const float* __restrict__ gna, float* __restrict__ out,
                        int N) {
    const float invN = 1.f / (float)N;
    const int t = blockIdx.x * blockDim.x + threadIdx.x;
    const int c0 = (t & 15) * 4;
    float am[4], w[4], b[4];
    #pragma unroll
    for (int j = 0; j < 4; j++) {
        int c = c0 + j;
        float mu  = g_colsum[c] * invN;
        float a   = gna[c] * mu;
        float ex2 = g_sumsq[c] * invN;
        float var = ex2 - 2.f * a * mu + a * a;
        am[j] = a;
        w[j]  = gnw[c] * rsqrtf(var + 1e-5f);
        b[j]  = gnb[c];
    }
    float4* o4 = reinterpret_cast<float4*>(out);
    const int total = N * 16;
    for (int i = t; i < total; i += gridDim.x * blockDim.x) {
        float4 h = o4[i];
        h.x = fmaf(h.x - am[0], w[0], b[0]);
        h.y = fmaf(h.y - am[1], w[1], b[1]);
        h.z = fmaf(h.z - am[2], w[2], b[2]);
        h.w = fmaf(h.w - am[3], w[3], b[3]);
        o4[i] = h;
    }
}

// ---------------------------------------------------------------------------
extern "C" void kernel_launch(void* const* d_in, const int* in_sizes, int n_in,
                              void* d_out, int out_size) {
    const float* x    = (const float*)d_in[0];
    const void*  ei   = d_in[1];
    const float* W0   = (const float*)d_in[2];
    const float* ln0w = (const float*)d_in[3];
    const float* ln0b = (const float*)d_in[4];
    const float* W1   = (const float*)d_in[5];
    const float* ln1w = (const float*)d_in[6];
    const float* ln1b = (const float*)d_in[7];
    const float* gnw  = (const float*)d_in[8];
    const float* gnb  = (const float*)d_in[9];
    const float* gna  = (const float*)d_in[10];

    const int N = in_sizes[0] / CH;
    const int E = in_sizes[1] / 2;
    float* out = (float*)d_out;

    k_init<<<64, 256>>>((const int*)ei, N, E);
    k_hist<<<(E + 1023) / 1024, 256>>>(ei, E);
    k_off<<<(N + 1023) / 1024, 1024>>>(N);
    k_fill<<<(E + 1023) / 1024, 256>>>(ei, E);

    const int ngroups = (N + 3) / 4;                 // warps needed
    const int mlp_blocks = (ngroups + 7) / 8;        // 8 warps per block
    k_mlp<<<mlp_blocks, 256>>>(x, W0, ln0w, ln0b, W1, ln1w, ln1b, out, N);

    k_final<<<2048, 256>>>(gnw, gnb, gna, out, N);
}

// round 6
// speedup vs baseline: 1.0538x; 1.0538x over previous
#include <cuda_runtime.h>

#define CH 64
#define MAXN 65536
#define MAXE 1100000

// Scratch (no allocs allowed).
__device__ int   g_deg[MAXN];
__device__ int   g_off[MAXN];
__device__ int   g_cursor[MAXN];
__device__ int   g_csr[MAXE];
__device__ int   g_total;
__device__ float g_colsum[CH];
__device__ float g_sumsq[CH];
__device__ int   g_idx64;

#define FFMA2(acc, a, b) \
    asm("fma.rn.f32x2 %0, %1, %2, %0;" : "+l"(acc) : "l"(a), "l"(b))
#define PACK2(out, lo, hi) \
    asm("mov.b64 %0, {%1, %2};" : "=l"(out) : "f"(lo), "f"(hi))
#define UNPACK2(lo, hi, in) \
    asm("mov.b64 {%0, %1}, %2;" : "=f"(lo), "=f"(hi) : "l"(in))

// ---------------------------------------------------------------------------
// K1: zero counters + reduction buffers, detect index dtype.
// ---------------------------------------------------------------------------
__global__ void k_init(const int* __restrict__ ei32, int N, int E) {
    for (int i = blockIdx.x * blockDim.x + threadIdx.x; i < N;
         i += gridDim.x * blockDim.x)
        g_deg[i] = 0;
    if (blockIdx.x == 0) {
        if (threadIdx.x < CH) {
            g_colsum[threadIdx.x] = 0.f;
            g_sumsq[threadIdx.x]  = 0.f;
        }
        if (threadIdx.x == 0) {
            g_total = 0;
            // int64 edge_index => high 32-bit word of every entry is 0.
            int allz = 1;
            int cnt = (E < 64) ? E : 64;
            for (int t = 0; t < cnt; t++) allz &= (ei32[2 * t + 1] == 0);
            g_idx64 = allz;
        }
    }
}

// ---------------------------------------------------------------------------
// K2: degree histogram (1 edge/thread — warp-parallelism hides atomic lat).
// ---------------------------------------------------------------------------
__global__ void k_hist(const void* __restrict__ ei, int E) {
    const int idx64 = g_idx64;
    const long long* e64 = (const long long*)ei;
    const int*       e32 = (const int*)ei;
    int i = blockIdx.x * blockDim.x + threadIdx.x;
    if (i < E) {
        int dst = idx64 ? (int)e64[E + i] : e32[E + i];
        atomicAdd(&g_deg[dst], 1);
    }
}

// ---------------------------------------------------------------------------
// K3: single-kernel offsets: block-local smem scan + atomic block base.
// ---------------------------------------------------------------------------
__global__ void k_off(int N) {
    __shared__ int s[1024];
    __shared__ int sbase;
    int tid = threadIdx.x;
    int i = blockIdx.x * 1024 + tid;
    int v = (i < N) ? g_deg[i] : 0;
    s[tid] = v;
    __syncthreads();
    for (int o = 1; o < 1024; o <<= 1) {
        int t = (tid >= o) ? s[tid - o] : 0;
        __syncthreads();
        s[tid] += t;
        __syncthreads();
    }
    if (tid == 1023) sbase = atomicAdd(&g_total, s[1023]);
    __syncthreads();
    if (i < N) {
        int o = sbase + s[tid] - v;
        g_off[i] = o;
        g_cursor[i] = o;
    }
}

// ---------------------------------------------------------------------------
// K4: fill CSR adjacency (1 edge/thread).
// ---------------------------------------------------------------------------
__global__ void k_fill(const void* __restrict__ ei, int E) {
    const int idx64 = g_idx64;
    const long long* e64 = (const long long*)ei;
    const int*       e32 = (const int*)ei;
    int i = blockIdx.x * blockDim.x + threadIdx.x;
    if (i < E) {
        int src, dst;
        if (idx64) { src = (int)e64[i]; dst = (int)e64[E + i]; }
        else       { src = e32[i];      dst = e32[E + i]; }
        int p = atomicAdd(&g_cursor[dst], 1);
        g_csr[p] = src;
    }
}

// ---------------------------------------------------------------------------
// Packed-pair 64x64 GEMM (f32x2): FFMA-pipe instrs halved; packs on ALU pipe.
// ---------------------------------------------------------------------------
__device__ __forceinline__ void gemm64_packed(
    const float4* __restrict__ wa, const float4* __restrict__ wb,
    const float* __restrict__ hrow0, const float* __restrict__ hrow1,
    const float* __restrict__ hrow2, const float* __restrict__ hrow3,
    float* a0, float* a1) {
    unsigned long long pa[2][2] = {{0ull, 0ull}, {0ull, 0ull}};
    const float4* h[4] = {
        reinterpret_cast<const float4*>(hrow0),
        reinterpret_cast<const float4*>(hrow1),
        reinterpret_cast<const float4*>(hrow2),
        reinterpret_cast<const float4*>(hrow3)};
    #pragma unroll
    for (int kk = 0; kk < 16; kk++) {
        float4 va = wa[kk];
        float4 vb = wb[kk];
        unsigned long long wax, way, waz, waw, wbx, wby, wbz, wbw;
        PACK2(wax, va.x, va.x); PACK2(way, va.y, va.y);
        PACK2(waz, va.z, va.z); PACK2(waw, va.w, va.w);
        PACK2(wbx, vb.x, vb.x); PACK2(wby, vb.y, vb.y);
        PACK2(wbz, vb.z, vb.z); PACK2(wbw, vb.w, vb.w);
        #pragma unroll
        for (int p = 0; p < 2; p++) {
            float4 h0 = h[2 * p][kk];
            float4 h1 = h[2 * p + 1][kk];
            unsigned long long hx, hy, hz, hw;
            PACK2(hx, h0.x, h1.x); PACK2(hy, h0.y, h1.y);
            PACK2(hz, h0.z, h1.z); PACK2(hw, h0.w, h1.w);
            FFMA2(pa[p][0], hx, wax); FFMA2(pa[p][0], hy, way);
            FFMA2(pa[p][0], hz, waz); FFMA2(pa[p][0], hw, waw);
            FFMA2(pa[p][1], hx, wbx); FFMA2(pa[p][1], hy, wby);
            FFMA2(pa[p][1], hz, wbz); FFMA2(pa[p][1], hw, wbw);
        }
    }
    #pragma unroll
    for (int p = 0; p < 2; p++) {
        UNPACK2(a0[2 * p], a0[2 * p + 1], pa[p][0]);
        UNPACK2(a1[2 * p], a1[2 * p + 1], pa[p][1]);
    }
}

// ---------------------------------------------------------------------------
// K5: fused gather + MLP + GraphNorm partial sums. Warp handles 4 rows.
// Gather uses 4 independent accumulator chains to keep 4+ loads in flight.
// ---------------------------------------------------------------------------
__global__ void k_mlp(const float* __restrict__ x,
                      const float* __restrict__ W0, const float* __restrict__ ln0w,
                      const float* __restrict__ ln0b, const float* __restrict__ W1,
                      const float* __restrict__ ln1w, const float* __restrict__ ln1b,
                      float* __restrict__ out, int N) {
    __shared__ __align__(16) float sW0[CH][68];
    __shared__ __align__(16) float sW1[CH][68];
    __shared__ __align__(16) float hbuf[8][4][CH];
    __shared__ float bsum[CH];
    __shared__ float bss[CH];

    const int tid  = threadIdx.x;
    const int lane = tid & 31;
    const int warp = tid >> 5;

    for (int i = tid; i < CH * CH; i += blockDim.x) {
        sW0[i >> 6][i & 63] = W0[i];
        sW1[i >> 6][i & 63] = W1[i];
    }
    if (tid < CH) { bsum[tid] = 0.f; bss[tid] = 0.f; }
    #pragma unroll
    for (int r = 0; r < 4; r++) {
        hbuf[warp][r][lane] = 0.f;
        hbuf[warp][r][lane + 32] = 0.f;
    }

    const float w0a = ln0w[lane], w0b = ln0w[lane + 32];
    const float b0a = ln0b[lane], b0b = ln0b[lane + 32];
    const float w1a = ln1w[lane], w1b = ln1w[lane + 32];
    const float b1a = ln1b[lane], b1b = ln1b[lane + 32];
    __syncthreads();

    const float4* wa0 = reinterpret_cast<const float4*>(&sW0[lane][0]);
    const float4* wb0 = reinterpret_cast<const float4*>(&sW0[lane + 32][0]);
    const float4* wa1 = reinterpret_cast<const float4*>(&sW1[lane][0]);
    const float4* wb1 = reinterpret_cast<const float4*>(&sW1[lane + 32][0]);
    const float2* x2  = reinterpret_cast<const float2*>(x);

    float cs0 = 0.f, cs1 = 0.f, ss0 = 0.f, ss1 = 0.f;

    const int gwarp  = blockIdx.x * 8 + warp;
    const int nwarps = gridDim.x * 8;

    for (int base = gwarp * 4; base < N; base += nwarps * 4) {
        // ---- gather: h = x[row] + sum of neighbor rows, 4 parallel chains ----
        #pragma unroll
        for (int r = 0; r < 4; r++) {
            int row = base + r;
            if (row < N) {
                int off = g_off[row];
                int deg = g_deg[row];
                float2 acc0 = x2[row * 32 + lane];
                float2 acc1 = make_float2(0.f, 0.f);
                float2 acc2 = make_float2(0.f, 0.f);
                float2 acc3 = make_float2(0.f, 0.f);
                int j = 0;
                for (; j + 4 <= deg; j += 4) {
                    int s0 = g_csr[off + j];
                    int s1 = g_csr[off + j + 1];
                    int s2 = g_csr[off + j + 2];
                    int s3 = g_csr[off + j + 3];
                    float2 v0 = x2[s0 * 32 + lane];
                    float2 v1 = x2[s1 * 32 + lane];
                    float2 v2 = x2[s2 * 32 + lane];
                    float2 v3 = x2[s3 * 32 + lane];
                    acc0.x += v0.x; acc0.y += v0.y;
                    acc1.x += v1.x; acc1.y += v1.y;
                    acc2.x += v2.x; acc2.y += v2.y;
                    acc3.x += v3.x; acc3.y += v3.y;
                }
                for (; j < deg; j++) {
                    int s0 = g_csr[off + j];
                    float2 v0 = x2[s0 * 32 + lane];
                    acc0.x += v0.x; acc0.y += v0.y;
                }
                acc0.x += acc1.x; acc0.y += acc1.y;
                acc2.x += acc3.x; acc2.y += acc3.y;
                acc0.x += acc2.x; acc0.y += acc2.y;
                reinterpret_cast<float2*>(&hbuf[warp][r][0])[lane] = acc0;
            }
        }
        __syncwarp();

        // ---- layer 0 GEMM ----
        float a0[4], a1[4];
        gemm64_packed(wa0, wb0, &hbuf[warp][0][0], &hbuf[warp][1][0],
                      &hbuf[warp][2][0], &hbuf[warp][3][0], a0, a1);
        __syncwarp();

        // ---- LayerNorm 0 + ReLU, restage ----
        #pragma unroll
        for (int r = 0; r < 4; r++) {
            float s = a0[r] + a1[r];
            #pragma unroll
            for (int o = 16; o; o >>= 1) s += __shfl_xor_sync(0xffffffffu, s, o);
            float mu = s * (1.f / 64.f);
            float d0 = a0[r] - mu, d1 = a1[r] - mu;
            float q = d0 * d0 + d1 * d1;
            #pragma unroll
            for (int o = 16; o; o >>= 1) q += __shfl_xor_sync(0xffffffffu, q, o);
            float inv = rsqrtf(q * (1.f / 64.f) + 1e-5f);
            hbuf[warp][r][lane]      = fmaxf(fmaf(d0 * inv, w0a, b0a), 0.f);
            hbuf[warp][r][lane + 32] = fmaxf(fmaf(d1 * inv, w0b, b0b), 0.f);
        }
        __syncwarp();

        // ---- layer 1 GEMM ----
        gemm64_packed(wa1, wb1, &hbuf[warp][0][0], &hbuf[warp][1][0],
                      &hbuf[warp][2][0], &hbuf[warp][3][0], a0, a1);

        // ---- LayerNorm 1 + ReLU + store + GraphNorm partials ----
        #pragma unroll
        for (int r = 0; r < 4; r++) {
            int row = base + r;
            float s = a0[r] + a1[r];
            #pragma unroll
            for (int o = 16; o; o >>= 1) s += __shfl_xor_sync(0xffffffffu, s, o);
            float mu = s * (1.f / 64.f);
            float d0 = a0[r] - mu, d1 = a1[r] - mu;
            float q = d0 * d0 + d1 * d1;
            #pragma unroll
            for (int o = 16; o; o >>= 1) q += __shfl_xor_sync(0xffffffffu, q, o);
            float inv = rsqrtf(q * (1.f / 64.f) + 1e-5f);
            float v0 = fmaxf(fmaf(d0 * inv, w1a, b1a), 0.f);
            float v1 = fmaxf(fmaf(d1 * inv, w1b, b1b), 0.f);
            if (row < N) {
                float* orow = out + (size_t)row * CH;
                orow[lane]      = v0;
                orow[lane + 32] = v1;
                cs0 += v0; cs1 += v1;
                ss0 = fmaf(v0, v0, ss0);
                ss1 = fmaf(v1, v1, ss1);
            }
        }
        __syncwarp();
    }

    // column sum / sumsq partials: register -> shared -> 128 global atomics.
    atomicAdd(&bsum[lane], cs0);
    atomicAdd(&bsum[lane + 32], cs1);
    atomicAdd(&bss[lane], ss0);
    atomicAdd(&bss[lane + 32], ss1);
    __syncthreads();
    if (tid < CH) {
        atomicAdd(&g_colsum[tid], bsum[tid]);
        atomicAdd(&g_sumsq[tid],  bss[tid]);
    }
}

// ---------------------------------------------------------------------------
// K6: final GraphNorm, in-place, float4. var = E[h^2] - 2*am*mu + am^2.
// ---------------------------------------------------------------------------
__global__ void k_final(const float* __restrict__ gnw, const float* __restrict__ gnb,
                        const float* __restrict__ gna, float* __restrict__ out,
                        int N) {
    const float invN = 1.f / (float)N;
    const int t = blockIdx.x * blockDim.x + threadIdx.x;
    const int c0 = (t & 15) * 4;
    float am[4], w[4], b[4];
    #pragma unroll
    for (int j = 0; j < 4; j++) {
        int c = c0 + j;
        float mu  = g_colsum[c] * invN;
        float a   = gna[c] * mu;
        float ex2 = g_sumsq[c] * invN;
        float var = ex2 - 2.f * a * mu + a * a;
        am[j] = a;
        w[j]  = gnw[c] * rsqrtf(var + 1e-5f);
        b[j]  = gnb[c];
    }
    float4* o4 = reinterpret_cast<float4*>(out);
    const int total = N * 16;
    for (int i = t; i < total; i += gridDim.x * blockDim.x) {
        float4 h = o4[i];
        h.x = fmaf(h.x - am[0], w[0], b[0]);
        h.y = fmaf(h.y - am[1], w[1], b[1]);
        h.z = fmaf(h.z - am[2], w[2], b[2]);
        h.w = fmaf(h.w - am[3], w[3], b[3]);
        o4[i] = h;
    }
}

// ---------------------------------------------------------------------------
extern "C" void kernel_launch(void* const* d_in, const int* in_sizes, int n_in,
                              void* d_out, int out_size) {
    const float* x    = (const float*)d_in[0];
    const void*  ei   = d_in[1];
    const float* W0   = (const float*)d_in[2];
    const float* ln0w = (const float*)d_in[3];
    const float* ln0b = (const float*)d_in[4];
    const float* W1   = (const float*)d_in[5];
    const float* ln1w = (const float*)d_in[6];
    const float* ln1b = (const float*)d_in[7];
    const float* gnw  = (const float*)d_in[8];
    const float* gnb  = (const float*)d_in[9];
    const float* gna  = (const float*)d_in[10];

    const int N = in_sizes[0] / CH;
    const int E = in_sizes[1] / 2;
    float* out = (float*)d_out;

    k_init<<<64, 256>>>((const int*)ei, N, E);
    k_hist<<<(E + 255) / 256, 256>>>(ei, E);
    k_off<<<(N + 1023) / 1024, 1024>>>(N);
    k_fill<<<(E + 255) / 256, 256>>>(ei, E);

    const int ngroups = (N + 3) / 4;                 // warps needed
    const int mlp_blocks = (ngroups + 7) / 8;        // 8 warps per block
    k_mlp<<<mlp_blocks, 256>>>(x, W0, ln0w, ln0b, W1, ln1w, ln1b, out, N);

    k_final<<<2048, 256>>>(gnw, gnb, gna, out, N);
}

// round 7
// speedup vs baseline: 1.0802x; 1.0250x over previous
#include <cuda_runtime.h>

#define CH 64
#define MAXN 65536
#define MAXE 1100000

// Scratch (no allocs allowed).
__device__ int   g_deg[MAXN];
__device__ int   g_off[MAXN];
__device__ int   g_rank[MAXE];
__device__ int   g_csr[MAXE];
__device__ int   g_total;
__device__ float g_colsum[CH];
__device__ float g_sumsq[CH];
__device__ int   g_idx64;

#define FFMA2(acc, a, b) \
    asm("fma.rn.f32x2 %0, %1, %2, %0;" : "+l"(acc) : "l"(a), "l"(b))
#define PACK2(out, lo, hi) \
    asm("mov.b64 %0, {%1, %2};" : "=l"(out) : "f"(lo), "f"(hi))
#define UNPACK2(lo, hi, in) \
    asm("mov.b64 {%0, %1}, %2;" : "=f"(lo), "=f"(hi) : "l"(in))

// ---------------------------------------------------------------------------
// K1: zero counters + reduction buffers, detect index dtype.
// ---------------------------------------------------------------------------
__global__ void k_init(const int* __restrict__ ei32, int N, int E) {
    for (int i = blockIdx.x * blockDim.x + threadIdx.x; i < N;
         i += gridDim.x * blockDim.x)
        g_deg[i] = 0;
    if (blockIdx.x == 0) {
        if (threadIdx.x < CH) {
            g_colsum[threadIdx.x] = 0.f;
            g_sumsq[threadIdx.x]  = 0.f;
        }
        if (threadIdx.x == 0) {
            g_total = 0;
            // int64 edge_index => high 32-bit word of every entry is 0.
            int allz = 1;
            int cnt = (E < 64) ? E : 64;
            for (int t = 0; t < cnt; t++) allz &= (ei32[2 * t + 1] == 0);
            g_idx64 = allz;
        }
    }
}

// ---------------------------------------------------------------------------
// K2: degree histogram. The atomic's return value IS this edge's rank within
// its destination bucket — store it so k_fill needs no atomic at all.
// ---------------------------------------------------------------------------
__global__ void k_hist(const void* __restrict__ ei, int E) {
    const int idx64 = g_idx64;
    const long long* e64 = (const long long*)ei;
    const int*       e32 = (const int*)ei;
    int i = blockIdx.x * blockDim.x + threadIdx.x;
    if (i < E) {
        int dst = idx64 ? (int)e64[E + i] : e32[E + i];
        g_rank[i] = atomicAdd(&g_deg[dst], 1);
    }
}

// ---------------------------------------------------------------------------
// K3: single-kernel offsets: block-local smem scan + atomic block base.
// ---------------------------------------------------------------------------
__global__ void k_off(int N) {
    __shared__ int s[1024];
    __shared__ int sbase;
    int tid = threadIdx.x;
    int i = blockIdx.x * 1024 + tid;
    int v = (i < N) ? g_deg[i] : 0;
    s[tid] = v;
    __syncthreads();
    for (int o = 1; o < 1024; o <<= 1) {
        int t = (tid >= o) ? s[tid - o] : 0;
        __syncthreads();
        s[tid] += t;
        __syncthreads();
    }
    if (tid == 1023) sbase = atomicAdd(&g_total, s[1023]);
    __syncthreads();
    if (i < N) g_off[i] = sbase + s[tid] - v;
}

// ---------------------------------------------------------------------------
// K4: CSR fill, atomic-free: slot = off[dst] + rank[i] (plain L2 load).
// ---------------------------------------------------------------------------
__global__ void k_fill(const void* __restrict__ ei, int E) {
    const int idx64 = g_idx64;
    const long long* e64 = (const long long*)ei;
    const int*       e32 = (const int*)ei;
    int i = blockIdx.x * blockDim.x + threadIdx.x;
    if (i < E) {
        int src, dst;
        if (idx64) { src = (int)e64[i]; dst = (int)e64[E + i]; }
        else       { src = e32[i];      dst = e32[E + i]; }
        g_csr[g_off[dst] + g_rank[i]] = src;
    }
}

// ---------------------------------------------------------------------------
// Packed-pair 64x64 GEMM (f32x2): FFMA-pipe instrs halved; packs on ALU pipe.
// ---------------------------------------------------------------------------
__device__ __forceinline__ void gemm64_packed(
    const float4* __restrict__ wa, const float4* __restrict__ wb,
    const float* __restrict__ hrow0, const float* __restrict__ hrow1,
    const float* __restrict__ hrow2, const float* __restrict__ hrow3,
    float* a0, float* a1) {
    unsigned long long pa[2][2] = {{0ull, 0ull}, {0ull, 0ull}};
    const float4* h[4] = {
        reinterpret_cast<const float4*>(hrow0),
        reinterpret_cast<const float4*>(hrow1),
        reinterpret_cast<const float4*>(hrow2),
        reinterpret_cast<const float4*>(hrow3)};
    #pragma unroll
    for (int kk = 0; kk < 16; kk++) {
        float4 va = wa[kk];
        float4 vb = wb[kk];
        unsigned long long wax, way, waz, waw, wbx, wby, wbz, wbw;
        PACK2(wax, va.x, va.x); PACK2(way, va.y, va.y);
        PACK2(waz, va.z, va.z); PACK2(waw, va.w, va.w);
        PACK2(wbx, vb.x, vb.x); PACK2(wby, vb.y, vb.y);
        PACK2(wbz, vb.z, vb.z); PACK2(wbw, vb.w, vb.w);
        #pragma unroll
        for (int p = 0; p < 2; p++) {
            float4 h0 = h[2 * p][kk];
            float4 h1 = h[2 * p + 1][kk];
            unsigned long long hx, hy, hz, hw;
            PACK2(hx, h0.x, h1.x); PACK2(hy, h0.y, h1.y);
            PACK2(hz, h0.z, h1.z); PACK2(hw, h0.w, h1.w);
            FFMA2(pa[p][0], hx, wax); FFMA2(pa[p][0], hy, way);
            FFMA2(pa[p][0], hz, waz); FFMA2(pa[p][0], hw, waw);
            FFMA2(pa[p][1], hx, wbx); FFMA2(pa[p][1], hy, wby);
            FFMA2(pa[p][1], hz, wbz); FFMA2(pa[p][1], hw, wbw);
        }
    }
    #pragma unroll
    for (int p = 0; p < 2; p++) {
        UNPACK2(a0[2 * p], a0[2 * p + 1], pa[p][0]);
        UNPACK2(a1[2 * p], a1[2 * p + 1], pa[p][1]);
    }
}

// ---------------------------------------------------------------------------
// K5: fused gather + MLP + GraphNorm partial sums. Warp handles 4 rows.
// Gather uses 4 independent accumulator chains to keep 4+ loads in flight.
// ---------------------------------------------------------------------------
__global__ void k_mlp(const float* __restrict__ x,
                      const float* __restrict__ W0, const float* __restrict__ ln0w,
                      const float* __restrict__ ln0b, const float* __restrict__ W1,
                      const float* __restrict__ ln1w, const float* __restrict__ ln1b,
                      float* __restrict__ out, int N) {
    __shared__ __align__(16) float sW0[CH][68];
    __shared__ __align__(16) float sW1[CH][68];
    __shared__ __align__(16) float hbuf[8][4][CH];
    __shared__ float bsum[CH];
    __shared__ float bss[CH];

    const int tid  = threadIdx.x;
    const int lane = tid & 31;
    const int warp = tid >> 5;

    for (int i = tid; i < CH * CH; i += blockDim.x) {
        sW0[i >> 6][i & 63] = W0[i];
        sW1[i >> 6][i & 63] = W1[i];
    }
    if (tid < CH) { bsum[tid] = 0.f; bss[tid] = 0.f; }
    #pragma unroll
    for (int r = 0; r < 4; r++) {
        hbuf[warp][r][lane] = 0.f;
        hbuf[warp][r][lane + 32] = 0.f;
    }

    const float w0a = ln0w[lane], w0b = ln0w[lane + 32];
    const float b0a = ln0b[lane], b0b = ln0b[lane + 32];
    const float w1a = ln1w[lane], w1b = ln1w[lane + 32];
    const float b1a = ln1b[lane], b1b = ln1b[lane + 32];
    __syncthreads();

    const float4* wa0 = reinterpret_cast<const float4*>(&sW0[lane][0]);
    const float4* wb0 = reinterpret_cast<const float4*>(&sW0[lane + 32][0]);
    const float4* wa1 = reinterpret_cast<const float4*>(&sW1[lane][0]);
    const float4* wb1 = reinterpret_cast<const float4*>(&sW1[lane + 32][0]);
    const float2* x2  = reinterpret_cast<const float2*>(x);

    float cs0 = 0.f, cs1 = 0.f, ss0 = 0.f, ss1 = 0.f;

    const int gwarp  = blockIdx.x * 8 + warp;
    const int nwarps = gridDim.x * 8;

    for (int base = gwarp * 4; base < N; base += nwarps * 4) {
        // ---- gather: h = x[row] + sum of neighbor rows, 4 parallel chains ----
        #pragma unroll
        for (int r = 0; r < 4; r++) {
            int row = base + r;
            if (row < N) {
                int off = g_off[row];
                int deg = g_deg[row];
                float2 acc0 = x2[row * 32 + lane];
                float2 acc1 = make_float2(0.f, 0.f);
                float2 acc2 = make_float2(0.f, 0.f);
                float2 acc3 = make_float2(0.f, 0.f);
                int j = 0;
                for (; j + 4 <= deg; j += 4) {
                    int s0 = g_csr[off + j];
                    int s1 = g_csr[off + j + 1];
                    int s2 = g_csr[off + j + 2];
                    int s3 = g_csr[off + j + 3];
                    float2 v0 = x2[s0 * 32 + lane];
                    float2 v1 = x2[s1 * 32 + lane];
                    float2 v2 = x2[s2 * 32 + lane];
                    float2 v3 = x2[s3 * 32 + lane];
                    acc0.x += v0.x; acc0.y += v0.y;
                    acc1.x += v1.x; acc1.y += v1.y;
                    acc2.x += v2.x; acc2.y += v2.y;
                    acc3.x += v3.x; acc3.y += v3.y;
                }
                for (; j < deg; j++) {
                    int s0 = g_csr[off + j];
                    float2 v0 = x2[s0 * 32 + lane];
                    acc0.x += v0.x; acc0.y += v0.y;
                }
                acc0.x += acc1.x; acc0.y += acc1.y;
                acc2.x += acc3.x; acc2.y += acc3.y;
                acc0.x += acc2.x; acc0.y += acc2.y;
                reinterpret_cast<float2*>(&hbuf[warp][r][0])[lane] = acc0;
            }
        }
        __syncwarp();

        // ---- layer 0 GEMM ----
        float a0[4], a1[4];
        gemm64_packed(wa0, wb0, &hbuf[warp][0][0], &hbuf[warp][1][0],
                      &hbuf[warp][2][0], &hbuf[warp][3][0], a0, a1);
        __syncwarp();

        // ---- LayerNorm 0 + ReLU, restage ----
        #pragma unroll
        for (int r = 0; r < 4; r++) {
            float s = a0[r] + a1[r];
            #pragma unroll
            for (int o = 16; o; o >>= 1) s += __shfl_xor_sync(0xffffffffu, s, o);
            float mu = s * (1.f / 64.f);
            float d0 = a0[r] - mu, d1 = a1[r] - mu;
            float q = d0 * d0 + d1 * d1;
            #pragma unroll
            for (int o = 16; o; o >>= 1) q += __shfl_xor_sync(0xffffffffu, q, o);
            float inv = rsqrtf(q * (1.f / 64.f) + 1e-5f);
            hbuf[warp][r][lane]      = fmaxf(fmaf(d0 * inv, w0a, b0a), 0.f);
            hbuf[warp][r][lane + 32] = fmaxf(fmaf(d1 * inv, w0b, b0b), 0.f);
        }
        __syncwarp();

        // ---- layer 1 GEMM ----
        gemm64_packed(wa1, wb1, &hbuf[warp][0][0], &hbuf[warp][1][0],
                      &hbuf[warp][2][0], &hbuf[warp][3][0], a0, a1);

        // ---- LayerNorm 1 + ReLU + store + GraphNorm partials ----
        #pragma unroll
        for (int r = 0; r < 4; r++) {
            int row = base + r;
            float s = a0[r] + a1[r];
            #pragma unroll
            for (int o = 16; o; o >>= 1) s += __shfl_xor_sync(0xffffffffu, s, o);
            float mu = s * (1.f / 64.f);
            float d0 = a0[r] - mu, d1 = a1[r] - mu;
            float q = d0 * d0 + d1 * d1;
            #pragma unroll
            for (int o = 16; o; o >>= 1) q += __shfl_xor_sync(0xffffffffu, q, o);
            float inv = rsqrtf(q * (1.f / 64.f) + 1e-5f);
            float v0 = fmaxf(fmaf(d0 * inv, w1a, b1a), 0.f);
            float v1 = fmaxf(fmaf(d1 * inv, w1b, b1b), 0.f);
            if (row < N) {
                float* orow = out + (size_t)row * CH;
                orow[lane]      = v0;
                orow[lane + 32] = v1;
                cs0 += v0; cs1 += v1;
                ss0 = fmaf(v0, v0, ss0);
                ss1 = fmaf(v1, v1, ss1);
            }
        }
        __syncwarp();
    }

    // column sum / sumsq partials: register -> shared -> 128 global atomics.
    atomicAdd(&bsum[lane], cs0);
    atomicAdd(&bsum[lane + 32], cs1);
    atomicAdd(&bss[lane], ss0);
    atomicAdd(&bss[lane + 32], ss1);
    __syncthreads();
    if (tid < CH) {
        atomicAdd(&g_colsum[tid], bsum[tid]);
        atomicAdd(&g_sumsq[tid],  bss[tid]);
    }
}

// ---------------------------------------------------------------------------
// K6: final GraphNorm, in-place, float4. var = E[h^2] - 2*am*mu + am^2.
// ---------------------------------------------------------------------------
__global__ void k_final(const float* __restrict__ gnw, const float* __restrict__ gnb,
                        const float* __restrict__ gna, float* __restrict__ out,
                        int N) {
    const float invN = 1.f / (float)N;
    const int t = blockIdx.x * blockDim.x + threadIdx.x;
    const int c0 = (t & 15) * 4;
    float am[4], w[4], b[4];
    #pragma unroll
    for (int j = 0; j < 4; j++) {
        int c = c0 + j;
        float mu  = g_colsum[c] * invN;
        float a   = gna[c] * mu;
        float ex2 = g_sumsq[c] * invN;
        float var = ex2 - 2.f * a * mu + a * a;
        am[j] = a;
        w[j]  = gnw[c] * rsqrtf(var + 1e-5f);
        b[j]  = gnb[c];
    }
    float4* o4 = reinterpret_cast<float4*>(out);
    const int total = N * 16;
    for (int i = t; i < total; i += gridDim.x * blockDim.x) {
        float4 h = o4[i];
        h.x = fmaf(h.x - am[0], w[0], b[0]);
        h.y = fmaf(h.y - am[1], w[1], b[1]);
        h.z = fmaf(h.z - am[2], w[2], b[2]);
        h.w = fmaf(h.w - am[3], w[3], b[3]);
        o4[i] = h;
    }
}

// ---------------------------------------------------------------------------
extern "C" void kernel_launch(void* const* d_in, const int* in_sizes, int n_in,
                              void* d_out, int out_size) {
    const float* x    = (const float*)d_in[0];
    const void*  ei   = d_in[1];
    const float* W0   = (const float*)d_in[2];
    const float* ln0w = (const float*)d_in[3];
    const float* ln0b = (const float*)d_in[4];
    const float* W1   = (const float*)d_in[5];
    const float* ln1w = (const float*)d_in[6];
    const float* ln1b = (const float*)d_in[7];
    const float* gnw  = (const float*)d_in[8];
    const float* gnb  = (const float*)d_in[9];
    const float* gna  = (const float*)d_in[10];

    const int N = in_sizes[0] / CH;
    const int E = in_sizes[1] / 2;
    float* out = (float*)d_out;

    k_init<<<64, 256>>>((const int*)ei, N, E);
    k_hist<<<(E + 255) / 256, 256>>>(ei, E);
    k_off<<<(N + 1023) / 1024, 1024>>>(N);
    k_fill<<<(E + 255) / 256, 256>>>(ei, E);

    const int ngroups = (N + 3) / 4;                 // warps needed
    const int mlp_blocks = (ngroups + 7) / 8;        // 8 warps per block
    k_mlp<<<mlp_blocks, 256>>>(x, W0, ln0w, ln0b, W1, ln1w, ln1b, out, N);

    k_final<<<2048, 256>>>(gnw, gnb, gna, out, N);
}